// round 10
// baseline (speedup 1.0000x reference)
#include <cuda_runtime.h>
#include <cuda_bf16.h>
#include <cstdint>

#define BB 4
#define NN 4096
#define MM 4096
#define DD 256

#define HALF (MM/2)           // 2048 targets per CTA
#define TILE_N 128            // targets per tile
#define NTILES (HALF/TILE_N)  // 16 tiles
#define NSTEPS (4*NTILES)     // 64 k-quarter steps

// smem per CTA: A 128 rows x 512B; B 2 bufs x (128 targets x 128B); yn 2x128 f32
#define OFF_A   0
#define A_BYTES (128*512)                 // 65536
#define OFF_B   A_BYTES
#define BQ      (128*128)                 // 16384 per k-quarter buffer
#define OFF_YN  (OFF_B + 2*BQ)            // 98304
#define SMEM_TOTAL (OFF_YN + 1024)        // 99328  (x2 CTAs = 198656 < 227KB)

// ---------------- device scratch (no allocs allowed) ----------------
__device__ __nv_bfloat16 g_xb16[BB * NN * DD];   // 8 MB
__device__ __nv_bfloat16 g_yb16[BB * MM * DD];   // 8 MB
__device__ float g_xnorm[BB * NN];
__device__ float g_ynorm[BB * MM];
__device__ int   g_rowmin[BB * NN];
__device__ int   g_done[BB];

// ---------------- helpers (plain-sm_100-compatible) ----------------
__device__ __forceinline__ uint32_t smem_u32(const void* p) {
    uint32_t a;
    asm("{ .reg .u64 t; cvta.to.shared.u64 t, %1; cvt.u32.u64 %0, t; }"
        : "=r"(a) : "l"(p));
    return a;
}
__device__ __forceinline__ void cp_async16(uint32_t dst, const void* src) {
    asm volatile("cp.async.cg.shared.global [%0], [%1], 16;" :: "r"(dst), "l"(src));
}
__device__ __forceinline__ void cp_async4(uint32_t dst, const void* src) {
    asm volatile("cp.async.ca.shared.global [%0], [%1], 4;" :: "r"(dst), "l"(src));
}
__device__ __forceinline__ void ldm_x4(uint32_t* r, uint32_t addr) {
    asm volatile("ldmatrix.sync.aligned.m8n8.x4.shared.b16 {%0,%1,%2,%3}, [%4];"
        : "=r"(r[0]), "=r"(r[1]), "=r"(r[2]), "=r"(r[3]) : "r"(addr));
}
__device__ __forceinline__ void mma16816(float* c, const uint32_t* a,
                                         uint32_t b0, uint32_t b1) {
    asm volatile(
        "mma.sync.aligned.m16n8k16.row.col.f32.bf16.bf16.f32 "
        "{%0,%1,%2,%3}, {%4,%5,%6,%7}, {%8,%9}, {%0,%1,%2,%3};"
        : "+f"(c[0]), "+f"(c[1]), "+f"(c[2]), "+f"(c[3])
        : "r"(a[0]), "r"(a[1]), "r"(a[2]), "r"(a[3]), "r"(b0), "r"(b1));
}

// ---------------------------------------------------------------------------
// Kernel 1: fp32 -> bf16 + exact fp32 row norms (warp per row); init rowmin.
// ---------------------------------------------------------------------------
__global__ void prep_kernel(const float* __restrict__ src,
                            const float* __restrict__ tgt) {
    int warp = (blockIdx.x * blockDim.x + threadIdx.x) >> 5;
    int lane = threadIdx.x & 31;
    if (blockIdx.x == 0 && threadIdx.x < BB) g_done[threadIdx.x] = 0;
    const int total = BB * NN + BB * MM;
    if (warp >= total) return;

    const float* base; __nv_bfloat16* obase; float* onorm; int row;
    bool isx = warp < BB * NN;
    if (isx) { base = src; obase = g_xb16; onorm = g_xnorm; row = warp; }
    else     { base = tgt; obase = g_yb16; onorm = g_ynorm; row = warp - BB * NN; }

    const float4* p = (const float4*)(base + (long long)row * DD);
    float4 v0 = p[2 * lane];
    float4 v1 = p[2 * lane + 1];
    float s = v0.x * v0.x + v0.y * v0.y + v0.z * v0.z + v0.w * v0.w
            + v1.x * v1.x + v1.y * v1.y + v1.z * v1.z + v1.w * v1.w;

    __nv_bfloat162 h0 = __floats2bfloat162_rn(v0.x, v0.y);
    __nv_bfloat162 h1 = __floats2bfloat162_rn(v0.z, v0.w);
    __nv_bfloat162 h2 = __floats2bfloat162_rn(v1.x, v1.y);
    __nv_bfloat162 h3 = __floats2bfloat162_rn(v1.z, v1.w);
    uint4 o;
    o.x = *(uint32_t*)&h0; o.y = *(uint32_t*)&h1;
    o.z = *(uint32_t*)&h2; o.w = *(uint32_t*)&h3;
    ((uint4*)(obase + (long long)row * DD))[lane] = o;

#pragma unroll
    for (int off = 16; off > 0; off >>= 1) s += __shfl_down_sync(0xffffffffu, s, off);
    if (lane == 0) {
        onorm[row] = s;
        if (isx) g_rowmin[row] = 0x7F800000;
    }
}

// ---------------------------------------------------------------------------
// Kernel 2: bf16 HMMA GEMM + row-min. CTA = 128 rows x 2048 targets,
// 4 warps (2M x 2N), warp tile 64x64. B pipelined at k-quarter (64-k)
// granularity (2 x 16KB buffers). 2 CTAs/SM. grid (64, 4) = 256 CTAs.
// ---------------------------------------------------------------------------
__global__ __launch_bounds__(128, 2)
void mincost_kernel(float* __restrict__ out) {
    extern __shared__ __align__(1024) char smem[];
    __shared__ int ticket_s;
    __shared__ float red_s[4];
    uint32_t sb = smem_u32(smem);
    const int tid  = threadIdx.x;
    const int w    = tid >> 5;
    const int lane = tid & 31;
    const int b    = blockIdx.y;
    const int mgrp = blockIdx.x >> 1;      // 0..31 (128-row group)
    const int half = blockIdx.x & 1;
    const int base_row = mgrp * 128;
    const int warpM = w >> 1;              // 0..1 (64 rows)
    const int warpN = w & 1;               // 0..1 (64 targets)
    const int groupID = lane >> 2;
    const int tig     = lane & 3;

    const __nv_bfloat16* xa  = g_xb16 + ((long long)b * NN + base_row) * DD;
    const __nv_bfloat16* yb  = g_yb16 + ((long long)b * MM + half * HALF) * DD;
    const float*         yng = g_ynorm + b * MM + half * HALF;

    // ---- initial loads: A (swizzled) + B quarter 0 of tile 0 + yn[0] ----
#pragma unroll
    for (int u = 0; u < 32; ++u) {
        int c = tid + 128 * u;              // 4096 chunks of 16B (128 rows x 32)
        int r = c >> 5, c16 = c & 31;
        cp_async16(sb + OFF_A + r * 512 + ((c16 ^ (r & 7)) << 4),
                   xa + r * DD + c16 * 8);
    }
#pragma unroll
    for (int u = 0; u < 8; ++u) {
        int c = tid + 128 * u;              // 1024 chunks (128 targets x 8)
        int r = c >> 3, c16 = c & 7;
        cp_async16(sb + OFF_B + r * 128 + ((c16 ^ (r & 7)) << 4),
                   yb + r * DD + c16 * 8);
    }
    if (tid < TILE_N) cp_async4(sb + OFF_YN + tid * 4, yng + tid);
    asm volatile("cp.async.commit_group;");

    // per-lane fragment addressing (XOR swizzle folded in per k-step)
    const int rowA = warpM * 64 + (lane & 15);
    const int hiA  = lane >> 4;
    const int rowB = warpN * 64 + (lane & 7) + ((lane >> 4) & 1) * 8;
    const int hiB  = (lane >> 3) & 1;
    const int rm   = lane & 7;
    const uint32_t aRow = sb + OFF_A + (uint32_t)rowA * 512;

    float rmin[8];
#pragma unroll
    for (int i = 0; i < 8; ++i) rmin[i] = 3.4e38f;

    float acc[4][8][4];

    for (int h = 0; h < NSTEPS; ++h) {
        const int buf = h & 1;
        const int q   = h & 3;
        const int jt  = h >> 2;

        asm volatile("cp.async.wait_group 0;");
        __syncthreads();

        // prefetch k-quarter h+1 into the other buffer (overlaps compute)
        if (h + 1 < NSTEPS) {
            const int jn = (h + 1) >> 2, qn = (h + 1) & 3;
            const __nv_bfloat16* yt = yb + (long long)jn * TILE_N * DD + qn * 64;
            uint32_t dstb = sb + OFF_B + (uint32_t)(buf ^ 1) * BQ;
#pragma unroll
            for (int u = 0; u < 8; ++u) {
                int c = tid + 128 * u;
                int r = c >> 3, c16 = c & 7;
                cp_async16(dstb + r * 128 + ((c16 ^ (r & 7)) << 4),
                           yt + r * DD + c16 * 8);
            }
            if (qn == 0 && tid < TILE_N)
                cp_async4(sb + OFF_YN + (jn & 1) * 512 + tid * 4,
                          yng + jn * TILE_N + tid);
            asm volatile("cp.async.commit_group;");
        }

        if (q == 0) {
#pragma unroll
            for (int mf = 0; mf < 4; ++mf)
#pragma unroll
                for (int nf = 0; nf < 8; ++nf)
#pragma unroll
                    for (int i = 0; i < 4; ++i) acc[mf][nf][i] = 0.0f;
        }

        const uint32_t bRow = sb + OFF_B + (uint32_t)buf * BQ
                            + (uint32_t)rowB * 128;
#pragma unroll
        for (int kk = 0; kk < 4; ++kk) {
            const int ks = q * 4 + kk;                       // abs k-step 0..15
            const uint32_t ac = (uint32_t)(((2 * ks + hiA) ^ rm) << 4);
            const uint32_t bc = (uint32_t)(((2 * kk + hiB) ^ rm) << 4);
            uint32_t afr[4][4], bfr[4][4];
#pragma unroll
            for (int mf = 0; mf < 4; ++mf)
                ldm_x4(afr[mf], aRow + (uint32_t)(mf * 16 * 512) + ac);
#pragma unroll
            for (int nf2 = 0; nf2 < 4; ++nf2)
                ldm_x4(bfr[nf2], bRow + (uint32_t)(nf2 * 16 * 128) + bc);
#pragma unroll
            for (int mf = 0; mf < 4; ++mf)
#pragma unroll
                for (int nf2 = 0; nf2 < 4; ++nf2)
#pragma unroll
                    for (int g = 0; g < 2; ++g)
                        mma16816(acc[mf][nf2 * 2 + g], afr[mf],
                                 bfr[nf2][g * 2], bfr[nf2][g * 2 + 1]);
        }

        // fold at tile end (after last k-quarter)
        if (q == 3) {
            const float* ynp = (const float*)(smem + OFF_YN + (jt & 1) * 512);
#pragma unroll
            for (int nf = 0; nf < 8; ++nf) {
                float y0 = ynp[warpN * 64 + nf * 8 + tig * 2];
                float y1 = ynp[warpN * 64 + nf * 8 + tig * 2 + 1];
#pragma unroll
                for (int mf = 0; mf < 4; ++mf) {
                    rmin[mf * 2] = fminf(rmin[mf * 2],
                        fminf(fmaf(-2.0f, acc[mf][nf][0], y0),
                              fmaf(-2.0f, acc[mf][nf][1], y1)));
                    rmin[mf * 2 + 1] = fminf(rmin[mf * 2 + 1],
                        fminf(fmaf(-2.0f, acc[mf][nf][2], y0),
                              fmaf(-2.0f, acc[mf][nf][3], y1)));
                }
            }
        }
    }

    // reduce over the 4 threads sharing each row, then global atomicMin
#pragma unroll
    for (int i = 0; i < 8; ++i) {
        rmin[i] = fminf(rmin[i], __shfl_xor_sync(0xffffffffu, rmin[i], 1));
        rmin[i] = fminf(rmin[i], __shfl_xor_sync(0xffffffffu, rmin[i], 2));
    }
    if (tig == 0) {
#pragma unroll
        for (int mf = 0; mf < 4; ++mf)
#pragma unroll
            for (int h8 = 0; h8 < 2; ++h8) {
                int row = base_row + warpM * 64 + mf * 16 + h8 * 8 + groupID;
                float xn = g_xnorm[b * NN + row];
                float cand = fmaxf(xn + rmin[mf * 2 + h8], 0.0f);
                atomicMin(&g_rowmin[b * NN + row], __float_as_int(cand));
            }
    }

    // ----- ticketed tail: last CTA of this batch computes the batch mean -----
    __threadfence();
    __syncthreads();
    if (tid == 0) ticket_s = atomicAdd(&g_done[b], 1);
    __syncthreads();
    if (ticket_s == 2 * (NN / 128) - 1) {      // 63: all 64 CTAs of batch b done
        __threadfence();
        const int4* p = (const int4*)(g_rowmin + b * NN);
        float s = 0.0f;
        for (int i = tid; i < NN / 4; i += 128) {
            int4 v = p[i];
            s += __int_as_float(v.x) + __int_as_float(v.y)
               + __int_as_float(v.z) + __int_as_float(v.w);
        }
#pragma unroll
        for (int o = 16; o > 0; o >>= 1) s += __shfl_down_sync(0xffffffffu, s, o);
        if (lane == 0) red_s[w] = s;
        __syncthreads();
        if (tid == 0) {
            float t = 0.0f;
#pragma unroll
            for (int wv = 0; wv < 4; ++wv) t += red_s[wv];
            out[b] = t * (1.0f / (float)NN);
        }
    }
}

// ---------------------------------------------------------------------------
extern "C" void kernel_launch(void* const* d_in, const int* in_sizes, int n_in,
                              void* d_out, int out_size) {
    const float* src = (const float*)d_in[0];
    const float* tgt = (const float*)d_in[1];
    float* out = (float*)d_out;

    cudaFuncSetAttribute(mincost_kernel,
                         cudaFuncAttributeMaxDynamicSharedMemorySize, SMEM_TOTAL);

    prep_kernel<<<BB * (NN + MM) / 8, 256>>>(src, tgt);
    mincost_kernel<<<dim3(64, 4), 128, SMEM_TOTAL>>>(out);
}

// round 12
// speedup vs baseline: 1.0774x; 1.0774x over previous
#include <cuda_runtime.h>
#include <cuda_bf16.h>
#include <cstdint>

#define BB 4
#define NN 4096
#define MM 4096
#define DD 256

#define HALF (MM/2)           // 2048 targets per CTA
#define TILE_N 128            // targets per tile
#define NTILES (HALF/TILE_N)  // 16 tiles
#define NHALVES (2*NTILES)    // 32 k-half steps

// smem: A 256 rows x 512B (swizzled); B 2 bufs x (128 rows x 256B); yn 2x128 f32
#define OFF_A   0
#define A_BYTES (256*512)                 // 131072
#define OFF_B   A_BYTES
#define BHALF   (128*256)                 // 32768 per k-half buffer
#define OFF_YN  (OFF_B + 2*BHALF)         // 196608
#define SMEM_TOTAL (OFF_YN + 1024)        // 197632

// ---------------- device scratch (no allocs allowed) ----------------
__device__ __nv_bfloat16 g_xb16[BB * NN * DD];   // 8 MB
__device__ __nv_bfloat16 g_yb16[BB * MM * DD];   // 8 MB
__device__ float g_xnorm[BB * NN];
__device__ float g_ynorm[BB * MM];
__device__ int   g_rowmin[BB * NN];
__device__ int   g_done[BB];

// ---------------- helpers (plain-sm_100-compatible) ----------------
__device__ __forceinline__ uint32_t smem_u32(const void* p) {
    uint32_t a;
    asm("{ .reg .u64 t; cvta.to.shared.u64 t, %1; cvt.u32.u64 %0, t; }"
        : "=r"(a) : "l"(p));
    return a;
}
__device__ __forceinline__ void cp_async16(uint32_t dst, const void* src) {
    asm volatile("cp.async.cg.shared.global [%0], [%1], 16;" :: "r"(dst), "l"(src));
}
__device__ __forceinline__ void cp_async4(uint32_t dst, const void* src) {
    asm volatile("cp.async.ca.shared.global [%0], [%1], 4;" :: "r"(dst), "l"(src));
}
__device__ __forceinline__ void ldm_x4(uint32_t* r, uint32_t addr) {
    asm volatile("ldmatrix.sync.aligned.m8n8.x4.shared.b16 {%0,%1,%2,%3}, [%4];"
        : "=r"(r[0]), "=r"(r[1]), "=r"(r[2]), "=r"(r[3]) : "r"(addr));
}
__device__ __forceinline__ void mma16816(float* c, const uint32_t* a,
                                         uint32_t b0, uint32_t b1) {
    asm volatile(
        "mma.sync.aligned.m16n8k16.row.col.f32.bf16.bf16.f32 "
        "{%0,%1,%2,%3}, {%4,%5,%6,%7}, {%8,%9}, {%0,%1,%2,%3};"
        : "+f"(c[0]), "+f"(c[1]), "+f"(c[2]), "+f"(c[3])
        : "r"(a[0]), "r"(a[1]), "r"(a[2]), "r"(a[3]), "r"(b0), "r"(b1));
}
// First k-step of a tile: D = A*B + 0 (C = zeros, D write-only) — no acc zeroing
__device__ __forceinline__ void mma16816_init(float* c, const uint32_t* a,
                                              uint32_t b0, uint32_t b1) {
    asm volatile(
        "mma.sync.aligned.m16n8k16.row.col.f32.bf16.bf16.f32 "
        "{%0,%1,%2,%3}, {%4,%5,%6,%7}, {%8,%9}, {%10,%11,%12,%13};"
        : "=f"(c[0]), "=f"(c[1]), "=f"(c[2]), "=f"(c[3])
        : "r"(a[0]), "r"(a[1]), "r"(a[2]), "r"(a[3]), "r"(b0), "r"(b1),
          "f"(0.0f), "f"(0.0f), "f"(0.0f), "f"(0.0f));
}

// One k-step: 8 ldmatrix + 32 MMAs (warp tile 64x64)
template <bool INIT>
__device__ __forceinline__ void do_kstep(float acc[4][8][4],
                                         uint32_t aRow, uint32_t bRow,
                                         int ks, int kk,
                                         int hiA, int hiB, int rm) {
    const uint32_t ac = (uint32_t)(((2 * ks + hiA) ^ rm) << 4);
    const uint32_t bc = (uint32_t)(((2 * kk + hiB) ^ rm) << 4);
    uint32_t afr[4][4], bfr[4][4];
#pragma unroll
    for (int mf = 0; mf < 4; ++mf)
        ldm_x4(afr[mf], aRow + (uint32_t)(mf * 16 * 512) + ac);
#pragma unroll
    for (int nf2 = 0; nf2 < 4; ++nf2)
        ldm_x4(bfr[nf2], bRow + (uint32_t)(nf2 * 16 * 256) + bc);
#pragma unroll
    for (int mf = 0; mf < 4; ++mf)
#pragma unroll
        for (int nf2 = 0; nf2 < 4; ++nf2)
#pragma unroll
            for (int g = 0; g < 2; ++g) {
                if (INIT)
                    mma16816_init(acc[mf][nf2 * 2 + g], afr[mf],
                                  bfr[nf2][g * 2], bfr[nf2][g * 2 + 1]);
                else
                    mma16816(acc[mf][nf2 * 2 + g], afr[mf],
                             bfr[nf2][g * 2], bfr[nf2][g * 2 + 1]);
            }
}

// ---------------------------------------------------------------------------
// Kernel 1: fp32 -> bf16 + exact fp32 row norms (warp per row); init rowmin.
// ---------------------------------------------------------------------------
__global__ void prep_kernel(const float* __restrict__ src,
                            const float* __restrict__ tgt) {
    int warp = (blockIdx.x * blockDim.x + threadIdx.x) >> 5;
    int lane = threadIdx.x & 31;
    if (blockIdx.x == 0 && threadIdx.x < BB) g_done[threadIdx.x] = 0;
    const int total = BB * NN + BB * MM;
    if (warp >= total) return;

    const float* base; __nv_bfloat16* obase; float* onorm; int row;
    bool isx = warp < BB * NN;
    if (isx) { base = src; obase = g_xb16; onorm = g_xnorm; row = warp; }
    else     { base = tgt; obase = g_yb16; onorm = g_ynorm; row = warp - BB * NN; }

    const float4* p = (const float4*)(base + (long long)row * DD);
    float4 v0 = p[2 * lane];
    float4 v1 = p[2 * lane + 1];
    float s = v0.x * v0.x + v0.y * v0.y + v0.z * v0.z + v0.w * v0.w
            + v1.x * v1.x + v1.y * v1.y + v1.z * v1.z + v1.w * v1.w;

    __nv_bfloat162 h0 = __floats2bfloat162_rn(v0.x, v0.y);
    __nv_bfloat162 h1 = __floats2bfloat162_rn(v0.z, v0.w);
    __nv_bfloat162 h2 = __floats2bfloat162_rn(v1.x, v1.y);
    __nv_bfloat162 h3 = __floats2bfloat162_rn(v1.z, v1.w);
    uint4 o;
    o.x = *(uint32_t*)&h0; o.y = *(uint32_t*)&h1;
    o.z = *(uint32_t*)&h2; o.w = *(uint32_t*)&h3;
    ((uint4*)(obase + (long long)row * DD))[lane] = o;

#pragma unroll
    for (int off = 16; off > 0; off >>= 1) s += __shfl_down_sync(0xffffffffu, s, off);
    if (lane == 0) {
        onorm[row] = s;
        if (isx) g_rowmin[row] = 0x7F800000;
    }
}

// ---------------------------------------------------------------------------
// Kernel 2: bf16 HMMA GEMM + row-min. Warp tile 64x64 (4Mx2N warps).
// CTA = 256 rows x 2048 targets, 16 tiles of 128 targets, B pipelined at
// k-half granularity (khalf0 -> buf0, khalf1 -> buf1, both compile-time).
// First MMA of each tile uses C=0 (no accumulator zeroing). grid (32,4).
// ---------------------------------------------------------------------------
__global__ __launch_bounds__(256, 1)
void mincost_kernel(float* __restrict__ out) {
    extern __shared__ __align__(1024) char smem[];
    __shared__ int ticket_s;
    __shared__ float red_s[8];
    uint32_t sb = smem_u32(smem);
    const int tid  = threadIdx.x;
    const int w    = tid >> 5;
    const int lane = tid & 31;
    const int b    = blockIdx.y;
    const int mgrp = blockIdx.x >> 1;
    const int half = blockIdx.x & 1;
    const int base_row = mgrp * 256;
    const int warpM = w >> 1;
    const int warpN = w & 1;
    const int groupID = lane >> 2;
    const int tig     = lane & 3;

    const __nv_bfloat16* xa  = g_xb16 + ((long long)b * NN + base_row) * DD;
    const __nv_bfloat16* yb  = g_yb16 + ((long long)b * MM + half * HALF) * DD;
    const float*         yng = g_ynorm + b * MM + half * HALF;

    // ---- initial loads: A (swizzled) + B k-half 0 of tile 0 + yn[0] ----
#pragma unroll
    for (int u = 0; u < 32; ++u) {
        int c = tid + 256 * u;
        int r = c >> 5, c16 = c & 31;
        cp_async16(sb + OFF_A + r * 512 + ((c16 ^ (r & 7)) << 4),
                   xa + r * DD + c16 * 8);
    }
#pragma unroll
    for (int u = 0; u < 8; ++u) {
        int c = tid + 256 * u;
        int r = c >> 4, c16 = c & 15;
        cp_async16(sb + OFF_B + r * 256 + ((c16 ^ (r & 7)) << 4),
                   yb + r * DD + c16 * 8);
    }
    if (tid < TILE_N) cp_async4(sb + OFF_YN + tid * 4, yng + tid);
    asm volatile("cp.async.commit_group;");

    const int rowA = warpM * 64 + (lane & 15);
    const int hiA  = lane >> 4;
    const int rowB = warpN * 64 + (lane & 7) + ((lane >> 4) & 1) * 8;
    const int hiB  = (lane >> 3) & 1;
    const int rm   = lane & 7;
    const uint32_t aRow  = sb + OFF_A + (uint32_t)rowA * 512;
    const uint32_t bRow0 = sb + OFF_B + (uint32_t)rowB * 256;           // buf0
    const uint32_t bRow1 = sb + OFF_B + BHALF + (uint32_t)rowB * 256;   // buf1

    float rmin[8];
#pragma unroll
    for (int i = 0; i < 8; ++i) rmin[i] = 3.4e38f;

    float acc[4][8][4];

    for (int jt = 0; jt < NTILES; ++jt) {
        // ================= k-half 0 (buf0, A ks 0..7) =================
        asm volatile("cp.async.wait_group 0;");
        __syncthreads();
        // prefetch k-half 1 of this tile into buf1
        {
            const __nv_bfloat16* yt = yb + (long long)jt * TILE_N * DD + 128;
#pragma unroll
            for (int u = 0; u < 8; ++u) {
                int c = tid + 256 * u;
                int r = c >> 4, c16 = c & 15;
                cp_async16(sb + OFF_B + BHALF + r * 256 + ((c16 ^ (r & 7)) << 4),
                           yt + r * DD + c16 * 8);
            }
            asm volatile("cp.async.commit_group;");
        }
        do_kstep<true>(acc, aRow, bRow0, 0, 0, hiA, hiB, rm);
#pragma unroll
        for (int kk = 1; kk < 8; ++kk)
            do_kstep<false>(acc, aRow, bRow0, kk, kk, hiA, hiB, rm);

        // ================= k-half 1 (buf1, A ks 8..15) =================
        asm volatile("cp.async.wait_group 0;");
        __syncthreads();
        // prefetch k-half 0 of next tile into buf0 (+ its yn)
        if (jt + 1 < NTILES) {
            const __nv_bfloat16* yt = yb + (long long)(jt + 1) * TILE_N * DD;
#pragma unroll
            for (int u = 0; u < 8; ++u) {
                int c = tid + 256 * u;
                int r = c >> 4, c16 = c & 15;
                cp_async16(sb + OFF_B + r * 256 + ((c16 ^ (r & 7)) << 4),
                           yt + r * DD + c16 * 8);
            }
            if (tid < TILE_N)
                cp_async4(sb + OFF_YN + ((jt + 1) & 1) * 512 + tid * 4,
                          yng + (jt + 1) * TILE_N + tid);
            asm volatile("cp.async.commit_group;");
        }
#pragma unroll
        for (int kk = 0; kk < 8; ++kk)
            do_kstep<false>(acc, aRow, bRow1, 8 + kk, kk, hiA, hiB, rm);

        // ---- fold tile into running per-thread row minima ----
        const float* ynp = (const float*)(smem + OFF_YN + (jt & 1) * 512);
#pragma unroll
        for (int nf = 0; nf < 8; ++nf) {
            float y0 = ynp[warpN * 64 + nf * 8 + tig * 2];
            float y1 = ynp[warpN * 64 + nf * 8 + tig * 2 + 1];
#pragma unroll
            for (int mf = 0; mf < 4; ++mf) {
                rmin[mf * 2] = fminf(rmin[mf * 2],
                    fminf(fmaf(-2.0f, acc[mf][nf][0], y0),
                          fmaf(-2.0f, acc[mf][nf][1], y1)));
                rmin[mf * 2 + 1] = fminf(rmin[mf * 2 + 1],
                    fminf(fmaf(-2.0f, acc[mf][nf][2], y0),
                          fmaf(-2.0f, acc[mf][nf][3], y1)));
            }
        }
    }

    // reduce over the 4 threads sharing each row, then global atomicMin
#pragma unroll
    for (int i = 0; i < 8; ++i) {
        rmin[i] = fminf(rmin[i], __shfl_xor_sync(0xffffffffu, rmin[i], 1));
        rmin[i] = fminf(rmin[i], __shfl_xor_sync(0xffffffffu, rmin[i], 2));
    }
    if (tig == 0) {
#pragma unroll
        for (int mf = 0; mf < 4; ++mf)
#pragma unroll
            for (int h8 = 0; h8 < 2; ++h8) {
                int row = base_row + warpM * 64 + mf * 16 + h8 * 8 + groupID;
                float xn = g_xnorm[b * NN + row];
                float cand = fmaxf(xn + rmin[mf * 2 + h8], 0.0f);
                atomicMin(&g_rowmin[b * NN + row], __float_as_int(cand));
            }
    }

    // ----- ticketed tail: last CTA of this batch computes the batch mean -----
    __threadfence();
    __syncthreads();
    if (tid == 0) ticket_s = atomicAdd(&g_done[b], 1);
    __syncthreads();
    if (ticket_s == 2 * (NN / 256) - 1) {
        __threadfence();
        const int4* p = (const int4*)(g_rowmin + b * NN);
        float s = 0.0f;
        for (int i = tid; i < NN / 4; i += 256) {
            int4 v = p[i];
            s += __int_as_float(v.x) + __int_as_float(v.y)
               + __int_as_float(v.z) + __int_as_float(v.w);
        }
#pragma unroll
        for (int o = 16; o > 0; o >>= 1) s += __shfl_down_sync(0xffffffffu, s, o);
        if (lane == 0) red_s[w] = s;
        __syncthreads();
        if (tid == 0) {
            float t = 0.0f;
#pragma unroll
            for (int wv = 0; wv < 8; ++wv) t += red_s[wv];
            out[b] = t * (1.0f / (float)NN);
        }
    }
}

// ---------------------------------------------------------------------------
extern "C" void kernel_launch(void* const* d_in, const int* in_sizes, int n_in,
                              void* d_out, int out_size) {
    const float* src = (const float*)d_in[0];
    const float* tgt = (const float*)d_in[1];
    float* out = (float*)d_out;

    cudaFuncSetAttribute(mincost_kernel,
                         cudaFuncAttributeMaxDynamicSharedMemorySize, SMEM_TOTAL);

    prep_kernel<<<BB * (NN + MM) / 8, 256>>>(src, tgt);
    mincost_kernel<<<dim3(32, 4), 256, SMEM_TOTAL>>>(out);
}